// round 11
// baseline (speedup 1.0000x reference)
#include <cuda_runtime.h>
#include <cuda_bf16.h>

#define HDIM 16
#define UDIM 7
#define HID  64
#define TMAX 100000
#define DTC  (5.0f / 60.0f)
#define KSC  2.885390081777926815f   // 2*log2(e): tanh-arg pre-scale
#define CHUNK 512
#define MAXCH ((TMAX + CHUNK - 1) / CHUNK + 1)

typedef unsigned long long u64;

// Scratch (no allocs allowed). g_pu padded 8 steps for branch-free batch-4 double-banked prefetch.
__device__ float g_pu[(TMAX + 8) * HID];   // KSC * (b1 + W1u @ u_t), [t][64]  (PRE-SCALED)
__device__ float g_z2[(TMAX + 8) * HID];   // z2_t history, [t][64] (+pad: rounded-up steps)
__device__ float g_yd[TMAX + CHUNK];
__device__ float g_yt[TMAX + CHUNK];
__device__ float g_yc[TMAX + CHUNK];
__device__ float g_ct[MAXCH * 3];
__device__ float g_off[MAXCH * 3];
__device__ float g_zc[MAXCH * HID];
__device__ float g_rw[3 * HID];            // wd@W3, wt@W3, wc@W3
__device__ float g_base[6];                // w@h0+b (3) ; w@b3 (3)

// ---------- packed f32x2 helpers ----------
__device__ __forceinline__ u64 pk2(float x, float y) {
    u64 r; asm("mov.b64 %0, {%1, %2};" : "=l"(r) : "f"(x), "f"(y)); return r;
}
__device__ __forceinline__ void upk2(u64 v, float& x, float& y) {
    asm("mov.b64 {%0, %1}, %2;" : "=f"(x), "=f"(y) : "l"(v));
}
__device__ __forceinline__ u64 ffma2(u64 a, u64 b, u64 c) {
    u64 d; asm("fma.rn.f32x2 %0, %1, %2, %3;" : "=l"(d) : "l"(a), "l"(b), "l"(c)); return d;
}
__device__ __forceinline__ u64 fadd2(u64 a, u64 b) {
    u64 d; asm("add.rn.f32x2 %0, %1, %2;" : "=l"(d) : "l"(a), "l"(b)); return d;
}
// tanh on a PRE-SCALED argument sx = KSC*x: tanh(x) = 1 - 2/(2^(sx)+1).
__device__ __forceinline__ float ftanh_s(float sx) {
    float e; asm("ex2.approx.f32 %0, %1;" : "=f"(e) : "f"(sx));
    float r; asm("rcp.approx.f32 %0, %1;" : "=f"(r) : "f"(e + 1.0f));
    return fmaf(-2.0f, r, 1.0f);
}

// ---------- pre-pass: g_pu[t][i] = KSC * (b1[i] + W1u row i @ u_t) ----------
__global__ void pre_kernel(const float* __restrict__ U,
                           const float* __restrict__ W1,
                           const float* __restrict__ b1, int T) {
    int idx = blockIdx.x * blockDim.x + threadIdx.x;
    if (idx >= (T + 8) * HID) return;
    int t = idx >> 6;
    int i = idx & 63;
    float s = 0.0f;
    if (t < T) {
        const float* u = U + t * UDIM;
        const float* w = W1 + i * (HDIM + UDIM) + HDIM;
        s = b1[i];
#pragma unroll
        for (int k = 0; k < UDIM; k++) s = fmaf(w[k], u[k], s);
        s *= KSC;
    }
    g_pu[idx] = s;
}

// ---------- prep: readout row projections and bases ----------
__global__ void prep_kernel(const float* __restrict__ W3,
                            const float* __restrict__ wd, const float* __restrict__ bd,
                            const float* __restrict__ wt, const float* __restrict__ bt,
                            const float* __restrict__ wc, const float* __restrict__ bc,
                            const float* __restrict__ b3, const float* __restrict__ h0) {
    int i = threadIdx.x;
    if (i < HID) {
        float sd = 0.f, st = 0.f, sc = 0.f;
#pragma unroll
        for (int k = 0; k < HDIM; k++) {
            float w3v = W3[k * HID + i];
            sd = fmaf(wd[k], w3v, sd);
            st = fmaf(wt[k], w3v, st);
            sc = fmaf(wc[k], w3v, sc);
        }
        g_rw[i] = sd; g_rw[HID + i] = st; g_rw[2 * HID + i] = sc;
    }
    if (i >= 64 && i < 67) {
        const float* w = (i == 64) ? wd : (i == 65) ? wt : wc;
        float bias = (i == 64) ? bd[0] : (i == 65) ? bt[0] : bc[0];
        float s = bias, sb = 0.f;
#pragma unroll
        for (int k = 0; k < HDIM; k++) { s = fmaf(w[k], h0[k], s); sb = fmaf(w[k], b3[k], sb); }
        g_base[i - 64] = s;        // w@h0 + b
        g_base[i - 61] = sb;       // w@b3
    }
}

// ---------- probe: no-op to keep seq_kernel in ncu's captured launch slot ----------
__global__ void probe_kernel() {}

// ---------- sequential scan: 1 block, 128 threads, 2 threads/row half-dots ----------
__global__ void __launch_bounds__(128, 1) seq_kernel(
    const float* __restrict__ W1, const float* __restrict__ b2v,
    const float* __restrict__ W2, const float* __restrict__ W3,
    const float* __restrict__ b3, const float* __restrict__ h0, int T) {

    __shared__ float w3s[HDIM * HID];       // staged W3 for Md precompute
    __shared__ float4 s_z1[HID / 4];
    __shared__ float4 s_z2[HID / 4];
    float* sz1 = (float*)s_z1;
    float* sz2 = (float*)s_z2;

    const int tid  = threadIdx.x;
    const int w    = tid >> 5;
    const int l    = tid & 31;
    const int row  = (w << 4) + (l & 15);   // 0..63 : this thread's z-row
    const int half = l >> 4;                // 0/1   : column half [half*32, +32)
    const int c0   = half * 32;             // column base

    // stage W3 into smem (128 threads x 8 elements)
#pragma unroll
    for (int k = 0; k < 8; k++) w3s[tid + 128 * k] = W3[tid + 128 * k];

    // W1h row (both halves of a row load the same — redundant but off critical path)
    float w1r[HDIM];
    {
        const float* ww = W1 + row * (HDIM + UDIM);
#pragma unroll
        for (int k = 0; k < HDIM; k++) w1r[k] = ww[k];
    }
    // scaled state: q = KSC * (W1h row @ h); cb = KSC*dt*(W1h row @ b3)
    float q = 0.f, cb = 0.f;
#pragma unroll
    for (int k = 0; k < HDIM; k++) { q = fmaf(w1r[k], h0[k], q); cb = fmaf(w1r[k], b3[k], cb); }
    q  *= KSC;
    cb *= KSC * DTC;

    __syncthreads();   // w3s ready

    // Md row slice = KSC*dt*(W1h row @ W3[:, c0..c0+32)), packed f32x2 (16 regs)
    u64 mdp[16];
#pragma unroll
    for (int p = 0; p < 16; p++) {
        float s0 = 0.f, s1 = 0.f;
#pragma unroll
        for (int k = 0; k < HDIM; k++) {
            s0 = fmaf(w1r[k], w3s[k * HID + c0 + 2 * p], s0);
            s1 = fmaf(w1r[k], w3s[k * HID + c0 + 2 * p + 1], s1);
        }
        mdp[p] = pk2(KSC * DTC * s0, KSC * DTC * s1);
    }
    // W2 row slice scaled by KSC, packed (16 regs)
    u64 w2p[16];
    {
        const float4* ww = (const float4*)(W2 + row * HID + c0);
#pragma unroll
        for (int k = 0; k < 8; k++) {
            float4 v = ww[k];
            w2p[2 * k]     = pk2(KSC * v.x, KSC * v.y);
            w2p[2 * k + 1] = pk2(KSC * v.z, KSC * v.w);
        }
    }
    // biases folded into half-0 accumulator only (avoid double add after butterfly)
    const float b2s = (half == 0) ? KSC * b2v[row] : 0.0f;
    const float cbs = (half == 0) ? cb : 0.0f;

    // first z1 (scaled pu[0])
    if (half == 0) sz1[row] = ftanh_s(q + g_pu[row]);
    __syncthreads();

    float* zst = g_z2 + row;          // running history pointer (half-1 writes)

    // deep prefetch: bank A holds pu[t+1..t+4] for the current 4-step batch
    float puA0 = g_pu[1 * HID + row];
    float puA1 = g_pu[2 * HID + row];
    float puA2 = g_pu[3 * HID + row];
    float puA3 = g_pu[4 * HID + row];
    const int nb4 = (T + 3) >> 2;     // 4-step batches (<=3 padded extra steps)

#define STEP(PU_NEXT)                                                          \
    {                                                                          \
        float tq = q + (PU_NEXT);     /* fully off-chain: ready at step top */ \
        const ulonglong2* zp = (const ulonglong2*)(sz1 + c0);                  \
        u64 a0 = pk2(b2s, 0.0f);                                               \
        u64 a1 = 0ull, a2 = 0ull, a3 = 0ull;                                   \
        _Pragma("unroll")                                                      \
        for (int k = 0; k < 8; k += 2) {                                       \
            ulonglong2 v0 = zp[k];                                             \
            ulonglong2 v1 = zp[k + 1];                                         \
            a0 = ffma2(w2p[2 * k],     v0.x, a0);                              \
            a1 = ffma2(w2p[2 * k + 1], v0.y, a1);                              \
            a2 = ffma2(w2p[2 * k + 2], v1.x, a2);                              \
            a3 = ffma2(w2p[2 * k + 3], v1.y, a3);                              \
        }                                                                      \
        float s0, s1;                                                          \
        upk2(fadd2(fadd2(a0, a1), fadd2(a2, a3)), s0, s1);                     \
        float ps = s0 + s1;                                                    \
        ps += __shfl_xor_sync(0xffffffffu, ps, 16);  /* combine halves */      \
        float z2 = ftanh_s(ps);                                                \
        if (half == 0) sz2[row] = z2;   /* STS on half0 path */                \
        else           *zst = z2;       /* history STG on idle half1 */        \
        zst += HID;                                                            \
        __syncthreads();                                                       \
        const ulonglong2* z2p = (const ulonglong2*)(sz2 + c0);                 \
        u64 p0 = pk2(cbs, 0.0f);                                               \
        u64 p1 = 0ull, p2 = 0ull, p3 = 0ull;                                   \
        _Pragma("unroll")                                                      \
        for (int k = 0; k < 8; k += 2) {                                       \
            ulonglong2 v0 = z2p[k];                                            \
            ulonglong2 v1 = z2p[k + 1];                                        \
            p0 = ffma2(mdp[2 * k],     v0.x, p0);                              \
            p1 = ffma2(mdp[2 * k + 1], v0.y, p1);                              \
            p2 = ffma2(mdp[2 * k + 2], v1.x, p2);                              \
            p3 = ffma2(mdp[2 * k + 3], v1.y, p3);                              \
        }                                                                      \
        float d0, d1;                                                          \
        upk2(fadd2(fadd2(p0, p1), fadd2(p2, p3)), d0, d1);                     \
        float dd = d0 + d1;                                                    \
        dd += __shfl_xor_sync(0xffffffffu, dd, 16);  /* full Md-row dot */     \
        q = q + dd;                   /* state update off the tanh chain */    \
        if (half == 0) sz1[row] = ftanh_s(tq + dd);                            \
        __syncthreads();                                                       \
    }

    for (int b = 0; b < nb4; b++) {
        int t4 = 4 * b;
        // bank B: issue LDGs a full batch (~600+ cyc) before first use
        float puB0 = g_pu[(t4 + 5) * HID + row];
        float puB1 = g_pu[(t4 + 6) * HID + row];
        float puB2 = g_pu[(t4 + 7) * HID + row];
        float puB3 = g_pu[(t4 + 8) * HID + row];
        STEP(puA0)
        STEP(puA1)
        STEP(puA2)
        STEP(puA3)
        puA0 = puB0; puA1 = puB1; puA2 = puB2; puA3 = puB3;
    }
#undef STEP
}

// ---------- post1: per-step readout increments y_t = rw @ z2_t + w@b3 ----------
__global__ void post1_kernel(int T) {
    int t = blockIdx.x * blockDim.x + threadIdx.x;
    if (t >= T) return;
    const float4* z = (const float4*)(g_z2 + t * HID);
    const float4* rd = (const float4*)g_rw;
    const float4* rt = (const float4*)(g_rw + HID);
    const float4* rc = (const float4*)(g_rw + 2 * HID);
    float d = 0.f, x = 0.f, c = 0.f;
#pragma unroll
    for (int k = 0; k < 16; k++) {
        float4 zv = z[k], a = rd[k], b = rt[k], e = rc[k];
        d = fmaf(zv.x, a.x, d); d = fmaf(zv.y, a.y, d); d = fmaf(zv.z, a.z, d); d = fmaf(zv.w, a.w, d);
        x = fmaf(zv.x, b.x, x); x = fmaf(zv.y, b.y, x); x = fmaf(zv.z, b.z, x); x = fmaf(zv.w, b.w, x);
        c = fmaf(zv.x, e.x, c); c = fmaf(zv.y, e.y, c); c = fmaf(zv.z, e.z, c); c = fmaf(zv.w, e.w, c);
    }
    g_yd[t] = d + g_base[3];
    g_yt[t] = x + g_base[4];
    g_yc[t] = c + g_base[5];
}

// ---------- scan stage 1: per-chunk scan -> local EXCLUSIVE + totals ----------
__global__ void scan1_kernel(int T) {
    __shared__ float sd[2][CHUNK], st[2][CHUNK], sc[2][CHUNK];
    int tid = threadIdx.x;
    int t = blockIdx.x * CHUNK + tid;
    float vd = (t < T) ? g_yd[t] : 0.f;
    float vt = (t < T) ? g_yt[t] : 0.f;
    float vc = (t < T) ? g_yc[t] : 0.f;
    sd[0][tid] = vd; st[0][tid] = vt; sc[0][tid] = vc;
    int pin = 0;
#pragma unroll
    for (int off = 1; off < CHUNK; off <<= 1) {
        __syncthreads();
        int po = 1 - pin;
        float ad = sd[pin][tid], at = st[pin][tid], ac = sc[pin][tid];
        if (tid >= off) { ad += sd[pin][tid - off]; at += st[pin][tid - off]; ac += sc[pin][tid - off]; }
        sd[po][tid] = ad; st[po][tid] = at; sc[po][tid] = ac;
        pin = po;
    }
    __syncthreads();
    if (t < T) {
        g_yd[t] = (tid > 0) ? sd[pin][tid - 1] : 0.f;
        g_yt[t] = (tid > 0) ? st[pin][tid - 1] : 0.f;
        g_yc[t] = (tid > 0) ? sc[pin][tid - 1] : 0.f;
    }
    if (tid == CHUNK - 1) {
        g_ct[blockIdx.x * 3 + 0] = sd[pin][tid];
        g_ct[blockIdx.x * 3 + 1] = st[pin][tid];
        g_ct[blockIdx.x * 3 + 2] = sc[pin][tid];
    }
}

// ---------- scan stage 2: exclusive scan of chunk totals ----------
__global__ void scan2_kernel(int nch) {
    int c = threadIdx.x;
    if (c >= 3) return;
    float run = 0.f;
    for (int ch = 0; ch < nch; ch++) {
        g_off[ch * 3 + c] = run;
        run += g_ct[ch * 3 + c];
    }
}

// ---------- scan stage 3: finalize outputs ----------
__global__ void scan3_kernel(float* __restrict__ out, int T) {
    int t = blockIdx.x * blockDim.x + threadIdx.x;
    if (t >= T) return;
    int ch = t / CHUNK;
    out[t]         = fmaf(DTC, g_off[ch * 3 + 0] + g_yd[t], g_base[0]);
    out[T + t]     = fmaf(DTC, g_off[ch * 3 + 1] + g_yt[t], g_base[1]);
    out[2 * T + t] = fmaf(DTC, g_off[ch * 3 + 2] + g_yc[t], g_base[2]);
}

// ---------- hT: chunked z2 reduction, then hT = h0 + dt*(W3@Sz + T*b3) ----------
__global__ void red1_kernel(int T) {
    int i = threadIdx.x;
    int t0 = blockIdx.x * CHUNK;
    float s = 0.f;
    for (int tt = 0; tt < CHUNK; tt++) {
        int t = t0 + tt;
        if (t < T) s += g_z2[t * HID + i];
    }
    g_zc[blockIdx.x * HID + i] = s;
}
__global__ void red2_kernel(const float* __restrict__ W3, const float* __restrict__ b3,
                            const float* __restrict__ h0, float* __restrict__ out,
                            int T, int nch) {
    __shared__ float Sz[HID];
    int i = threadIdx.x;
    float s = 0.f;
    for (int ch = 0; ch < nch; ch++) s += g_zc[ch * HID + i];
    Sz[i] = s;
    __syncthreads();
    if (i < HDIM) {
        float acc = (float)T * b3[i];
#pragma unroll
        for (int j = 0; j < HID; j++) acc = fmaf(W3[i * HID + j], Sz[j], acc);
        out[3 * T + i] = fmaf(DTC, acc, h0[i]);
    }
}

extern "C" void kernel_launch(void* const* d_in, const int* in_sizes, int n_in,
                              void* d_out, int out_size) {
    const float* U  = (const float*)d_in[0];
    const float* W1 = (const float*)d_in[1];
    const float* b1 = (const float*)d_in[2];
    const float* W2 = (const float*)d_in[3];
    const float* b2 = (const float*)d_in[4];
    const float* W3 = (const float*)d_in[5];
    const float* b3 = (const float*)d_in[6];
    const float* wd = (const float*)d_in[7];
    const float* bd = (const float*)d_in[8];
    const float* wt = (const float*)d_in[9];
    const float* bt = (const float*)d_in[10];
    const float* wc = (const float*)d_in[11];
    const float* bc = (const float*)d_in[12];
    const float* h0 = (const float*)d_in[13];
    float* out = (float*)d_out;

    int T = in_sizes[0] / UDIM;
    if (T > TMAX) T = TMAX;
    int nch = (T + CHUNK - 1) / CHUNK;

    pre_kernel<<<((T + 8) * HID + 255) / 256, 256>>>(U, W1, b1, T);
    prep_kernel<<<1, 128>>>(W3, wd, bd, wt, bt, wc, bc, b3, h0);
    probe_kernel<<<1, 32>>>();   // keeps seq_kernel in ncu's captured launch slot
    seq_kernel<<<1, 128>>>(W1, b2, W2, W3, b3, h0, T);
    post1_kernel<<<(T + 255) / 256, 256>>>(T);
    scan1_kernel<<<nch, CHUNK>>>(T);
    scan2_kernel<<<1, 4>>>(nch);
    scan3_kernel<<<(T + 255) / 256, 256>>>(out, T);
    red1_kernel<<<nch, HID>>>(T);
    red2_kernel<<<1, HID>>>(W3, b3, h0, out, T, nch);
}

// round 13
// speedup vs baseline: 1.0243x; 1.0243x over previous
#include <cuda_runtime.h>
#include <cuda_bf16.h>

#define HDIM 16
#define UDIM 7
#define HID  64
#define TMAX 100000
#define DTC  (5.0f / 60.0f)
#define KSC  2.885390081777926815f   // 2*log2(e): tanh-arg pre-scale
#define CHUNK 512
#define MAXCH ((TMAX + CHUNK - 1) / CHUNK + 1)

typedef unsigned long long u64;

// Scratch (no allocs allowed). g_pu padded for branch-free depth-2 prefetch.
__device__ float g_pu[(TMAX + 8) * HID];   // KSC * (b1 + W1u @ u_t), [t][64]  (PRE-SCALED)
__device__ float g_z2[(TMAX + 8) * HID];   // z2_t history (z-form!), [t][64]
__device__ float g_yd[TMAX + CHUNK];
__device__ float g_yt[TMAX + CHUNK];
__device__ float g_yc[TMAX + CHUNK];
__device__ float g_ct[MAXCH * 3];
__device__ float g_off[MAXCH * 3];
__device__ float g_zc[MAXCH * HID];
__device__ float g_rw[3 * HID];            // wd@W3, wt@W3, wc@W3  (z-form, as in best-passing run)
__device__ float g_base[6];                // w@h0+b (3) ; w@b3 (3)

// ---------- packed f32x2 helpers ----------
__device__ __forceinline__ u64 pk2(float x, float y) {
    u64 r; asm("mov.b64 %0, {%1, %2};" : "=l"(r) : "f"(x), "f"(y)); return r;
}
__device__ __forceinline__ void upk2(u64 v, float& x, float& y) {
    asm("mov.b64 {%0, %1}, %2;" : "=f"(x), "=f"(y) : "l"(v));
}
__device__ __forceinline__ u64 ffma2(u64 a, u64 b, u64 c) {
    u64 d; asm("fma.rn.f32x2 %0, %1, %2, %3;" : "=l"(d) : "l"(a), "l"(b), "l"(c)); return d;
}
__device__ __forceinline__ u64 fadd2(u64 a, u64 b) {
    u64 d; asm("add.rn.f32x2 %0, %1, %2;" : "=l"(d) : "l"(a), "l"(b)); return d;
}
// r-form activation on PRE-SCALED arg s = KSC*x: r = 1/(2^s + 1); tanh(x) = 1 - 2r.
__device__ __forceinline__ float fsig(float s) {
    float e; asm("ex2.approx.f32 %0, %1;" : "=f"(e) : "f"(s));
    float r; asm("rcp.approx.f32 %0, %1;" : "=f"(r) : "f"(e + 1.0f));
    return r;
}

// ---------- pre-pass: g_pu[t][i] = KSC * (b1[i] + W1u row i @ u_t) ----------
__global__ void pre_kernel(const float* __restrict__ U,
                           const float* __restrict__ W1,
                           const float* __restrict__ b1, int T) {
    int idx = blockIdx.x * blockDim.x + threadIdx.x;
    if (idx >= (T + 8) * HID) return;
    int t = idx >> 6;
    int i = idx & 63;
    float s = 0.0f;
    if (t < T) {
        const float* u = U + t * UDIM;
        const float* w = W1 + i * (HDIM + UDIM) + HDIM;
        s = b1[i];
#pragma unroll
        for (int k = 0; k < UDIM; k++) s = fmaf(w[k], u[k], s);
        s *= KSC;
    }
    g_pu[idx] = s;
}

// ---------- prep: readout row projections and bases (z-form, identical to best run) ----------
__global__ void prep_kernel(const float* __restrict__ W3,
                            const float* __restrict__ wd, const float* __restrict__ bd,
                            const float* __restrict__ wt, const float* __restrict__ bt,
                            const float* __restrict__ wc, const float* __restrict__ bc,
                            const float* __restrict__ b3, const float* __restrict__ h0) {
    int i = threadIdx.x;
    if (i < HID) {
        float sd = 0.f, st = 0.f, sc = 0.f;
#pragma unroll
        for (int k = 0; k < HDIM; k++) {
            float w3v = W3[k * HID + i];
            sd = fmaf(wd[k], w3v, sd);
            st = fmaf(wt[k], w3v, st);
            sc = fmaf(wc[k], w3v, sc);
        }
        g_rw[i] = sd; g_rw[HID + i] = st; g_rw[2 * HID + i] = sc;
    }
    if (i >= 64 && i < 67) {
        const float* w = (i == 64) ? wd : (i == 65) ? wt : wc;
        float bias = (i == 64) ? bd[0] : (i == 65) ? bt[0] : bc[0];
        float s = bias, sb = 0.f;
#pragma unroll
        for (int k = 0; k < HDIM; k++) { s = fmaf(w[k], h0[k], s); sb = fmaf(w[k], b3[k], sb); }
        g_base[i - 64] = s;        // w@h0 + b
        g_base[i - 61] = sb;       // w@b3
    }
}

// ---------- probe: no-op to keep seq_kernel in ncu's captured launch slot ----------
__global__ void probe_kernel() {}

// ---------- sequential scan: 1 block, 128 threads, r-form exchange + exact q tracking ----------
__global__ void __launch_bounds__(128, 1) seq_kernel(
    const float* __restrict__ W1, const float* __restrict__ b2v,
    const float* __restrict__ W2, const float* __restrict__ W3,
    const float* __restrict__ b3, const float* __restrict__ h0, int T) {

    __shared__ float w3s[HDIM * HID];       // staged W3 for Md precompute
    __shared__ float4 s_z1[HID / 4];        // r1 values
    __shared__ float4 s_z2[HID / 4];        // r2 values
    float* sz1 = (float*)s_z1;
    float* sz2 = (float*)s_z2;

    const int tid  = threadIdx.x;
    const int w_   = tid >> 5;
    const int l    = tid & 31;
    const int row  = (w_ << 4) + (l & 15);  // 0..63 : this thread's z-row
    const int half = l >> 4;                // 0/1   : column half [half*32, +32)
    const int c0   = half * 32;             // column base

    // stage W3 into smem (128 threads x 8 elements)
#pragma unroll
    for (int k = 0; k < 8; k++) w3s[tid + 128 * k] = W3[tid + 128 * k];

    // W1h row
    float w1r[HDIM];
    {
        const float* ww = W1 + row * (HDIM + UDIM);
#pragma unroll
        for (int k = 0; k < HDIM; k++) w1r[k] = ww[k];
    }
    // q0 = KSC*(W1h row @ h0) ; bsum = W1h row @ b3
    float q = 0.f, bsum = 0.f;
#pragma unroll
    for (int k = 0; k < HDIM; k++) { q = fmaf(w1r[k], h0[k], q); bsum = fmaf(w1r[k], b3[k], bsum); }
    q *= KSC;

    __syncthreads();   // w3s ready

    // Md slice = W1h row @ W3[:, c0..c0+32); packed as -2*KSC*DTC (r-form fold).
    // msum: unscaled slice row-sum, butterflied to the full 64-col sum.
    u64 mdp[16];
    float msum = 0.f;
#pragma unroll
    for (int p = 0; p < 16; p++) {
        float s0 = 0.f, s1 = 0.f;
#pragma unroll
        for (int k = 0; k < HDIM; k++) {
            s0 = fmaf(w1r[k], w3s[k * HID + c0 + 2 * p], s0);
            s1 = fmaf(w1r[k], w3s[k * HID + c0 + 2 * p + 1], s1);
        }
        mdp[p] = pk2(-2.f * KSC * DTC * s0, -2.f * KSC * DTC * s1);
        msum += s0 + s1;
    }
    msum += __shfl_xor_sync(0xffffffffu, msum, 16);
    // q-update constant: KSC*DTC*(W1h@b3) + KSC*DTC*rowsum(Md)  (z=1-2r fold), half0 init only
    const float cbs = (half == 0) ? KSC * DTC * (bsum + msum) : 0.0f;

    // W2 slice packed as -2*KSC*W2 (r-form fold); wsum = unscaled slice row-sum
    u64 w2p[16];
    float wsum = 0.f;
    {
        const float4* ww = (const float4*)(W2 + row * HID + c0);
#pragma unroll
        for (int k = 0; k < 8; k++) {
            float4 v = ww[k];
            w2p[2 * k]     = pk2(-2.f * KSC * v.x, -2.f * KSC * v.y);
            w2p[2 * k + 1] = pk2(-2.f * KSC * v.z, -2.f * KSC * v.w);
            wsum += (v.x + v.y) + (v.z + v.w);
        }
    }
    wsum += __shfl_xor_sync(0xffffffffu, wsum, 16);
    const float b2s = (half == 0) ? KSC * (b2v[row] + wsum) : 0.0f;

    // first z1 (r-form)
    if (half == 0) sz1[row] = fsig(q + g_pu[row]);
    __syncthreads();

    float* zst = g_z2 + row;          // z-form history pointer (half-1 writes)
    float pu1 = g_pu[HID + row];      // pu[1] (scaled)
    const int nb2 = (T + 1) >> 1;     // step pairs (<=1 padded extra step)

#define STEP(PU_NEXT)                                                          \
    {                                                                          \
        float tq = q + (PU_NEXT);     /* off-chain: both operands ready */     \
        const ulonglong2* zp = (const ulonglong2*)(sz1 + c0);                  \
        u64 a0 = pk2(b2s, 0.0f);      /* bias + rowsum fold in init */         \
        u64 a1 = 0ull, a2 = 0ull, a3 = 0ull;                                   \
        _Pragma("unroll")                                                      \
        for (int k = 0; k < 8; k += 2) {                                       \
            ulonglong2 v0 = zp[k];                                             \
            ulonglong2 v1 = zp[k + 1];                                         \
            a0 = ffma2(w2p[2 * k],     v0.x, a0);                              \
            a1 = ffma2(w2p[2 * k + 1], v0.y, a1);                              \
            a2 = ffma2(w2p[2 * k + 2], v1.x, a2);                              \
            a3 = ffma2(w2p[2 * k + 3], v1.y, a3);                              \
        }                                                                      \
        float s0, s1;                                                          \
        upk2(fadd2(fadd2(a0, a1), fadd2(a2, a3)), s0, s1);                     \
        float ps = s0 + s1;                                                    \
        ps += __shfl_xor_sync(0xffffffffu, ps, 16);  /* combine halves */      \
        float r2 = fsig(ps);          /* chain ends at rcp: no -2 fma */       \
        if (half == 0) sz2[row] = r2;                /* STS for stage C */     \
        else           *zst = fmaf(-2.f, r2, 1.f);   /* z-form history STG */  \
        zst += HID;                                                            \
        __syncthreads();                                                       \
        const ulonglong2* z2p = (const ulonglong2*)(sz2 + c0);                 \
        u64 p0 = pk2(cbs, 0.0f);      /* constant fold in init */              \
        u64 p1 = 0ull, p2 = 0ull, p3 = 0ull;                                   \
        _Pragma("unroll")                                                      \
        for (int k = 0; k < 8; k += 2) {                                       \
            ulonglong2 v0 = z2p[k];                                            \
            ulonglong2 v1 = z2p[k + 1];                                        \
            p0 = ffma2(mdp[2 * k],     v0.x, p0);                              \
            p1 = ffma2(mdp[2 * k + 1], v0.y, p1);                              \
            p2 = ffma2(mdp[2 * k + 2], v1.x, p2);                              \
            p3 = ffma2(mdp[2 * k + 3], v1.y, p3);                              \
        }                                                                      \
        float d0, d1;                                                          \
        upk2(fadd2(fadd2(p0, p1), fadd2(p2, p3)), d0, d1);                     \
        float dd = d0 + d1;                                                    \
        dd += __shfl_xor_sync(0xffffffffu, dd, 16);  /* full q-increment */    \
        q = q + dd;                   /* EXACT state tracking (as best run) */ \
        if (half == 0) sz1[row] = fsig(tq + dd);     /* r-form: no -2 fma */   \
        __syncthreads();                                                       \
    }

    for (int b = 0; b < nb2; b++) {
        int t = 2 * b;
        float pu2  = g_pu[(t + 2) * HID + row];   // used end of first STEP
        float pu1n = g_pu[(t + 3) * HID + row];   // used end of second STEP
        STEP(pu1)
        STEP(pu2)
        pu1 = pu1n;
    }
#undef STEP
}

// ---------- post1: per-step readout increments y_t = rw @ z2_t + w@b3 (z-form) ----------
__global__ void post1_kernel(int T) {
    int t = blockIdx.x * blockDim.x + threadIdx.x;
    if (t >= T) return;
    const float4* z = (const float4*)(g_z2 + t * HID);
    const float4* rd = (const float4*)g_rw;
    const float4* rt = (const float4*)(g_rw + HID);
    const float4* rc = (const float4*)(g_rw + 2 * HID);
    float d = 0.f, x = 0.f, c = 0.f;
#pragma unroll
    for (int k = 0; k < 16; k++) {
        float4 zv = z[k], a = rd[k], b = rt[k], e = rc[k];
        d = fmaf(zv.x, a.x, d); d = fmaf(zv.y, a.y, d); d = fmaf(zv.z, a.z, d); d = fmaf(zv.w, a.w, d);
        x = fmaf(zv.x, b.x, x); x = fmaf(zv.y, b.y, x); x = fmaf(zv.z, b.z, x); x = fmaf(zv.w, b.w, x);
        c = fmaf(zv.x, e.x, c); c = fmaf(zv.y, e.y, c); c = fmaf(zv.z, e.z, c); c = fmaf(zv.w, e.w, c);
    }
    g_yd[t] = d + g_base[3];
    g_yt[t] = x + g_base[4];
    g_yc[t] = c + g_base[5];
}

// ---------- scan stage 1: per-chunk scan -> local EXCLUSIVE + totals ----------
__global__ void scan1_kernel(int T) {
    __shared__ float sd[2][CHUNK], st[2][CHUNK], sc[2][CHUNK];
    int tid = threadIdx.x;
    int t = blockIdx.x * CHUNK + tid;
    float vd = (t < T) ? g_yd[t] : 0.f;
    float vt = (t < T) ? g_yt[t] : 0.f;
    float vc = (t < T) ? g_yc[t] : 0.f;
    sd[0][tid] = vd; st[0][tid] = vt; sc[0][tid] = vc;
    int pin = 0;
#pragma unroll
    for (int off = 1; off < CHUNK; off <<= 1) {
        __syncthreads();
        int po = 1 - pin;
        float ad = sd[pin][tid], at = st[pin][tid], ac = sc[pin][tid];
        if (tid >= off) { ad += sd[pin][tid - off]; at += st[pin][tid - off]; ac += sc[pin][tid - off]; }
        sd[po][tid] = ad; st[po][tid] = at; sc[po][tid] = ac;
        pin = po;
    }
    __syncthreads();
    if (t < T) {
        g_yd[t] = (tid > 0) ? sd[pin][tid - 1] : 0.f;
        g_yt[t] = (tid > 0) ? st[pin][tid - 1] : 0.f;
        g_yc[t] = (tid > 0) ? sc[pin][tid - 1] : 0.f;
    }
    if (tid == CHUNK - 1) {
        g_ct[blockIdx.x * 3 + 0] = sd[pin][tid];
        g_ct[blockIdx.x * 3 + 1] = st[pin][tid];
        g_ct[blockIdx.x * 3 + 2] = sc[pin][tid];
    }
}

// ---------- scan stage 2: exclusive scan of chunk totals ----------
__global__ void scan2_kernel(int nch) {
    int c = threadIdx.x;
    if (c >= 3) return;
    float run = 0.f;
    for (int ch = 0; ch < nch; ch++) {
        g_off[ch * 3 + c] = run;
        run += g_ct[ch * 3 + c];
    }
}

// ---------- scan stage 3: finalize outputs ----------
__global__ void scan3_kernel(float* __restrict__ out, int T) {
    int t = blockIdx.x * blockDim.x + threadIdx.x;
    if (t >= T) return;
    int ch = t / CHUNK;
    out[t]         = fmaf(DTC, g_off[ch * 3 + 0] + g_yd[t], g_base[0]);
    out[T + t]     = fmaf(DTC, g_off[ch * 3 + 1] + g_yt[t], g_base[1]);
    out[2 * T + t] = fmaf(DTC, g_off[ch * 3 + 2] + g_yc[t], g_base[2]);
}

// ---------- hT: chunked z2 reduction, then hT = h0 + dt*(W3@Sz + T*b3) ----------
__global__ void red1_kernel(int T) {
    int i = threadIdx.x;
    int t0 = blockIdx.x * CHUNK;
    float s = 0.f;
    for (int tt = 0; tt < CHUNK; tt++) {
        int t = t0 + tt;
        if (t < T) s += g_z2[t * HID + i];
    }
    g_zc[blockIdx.x * HID + i] = s;
}
__global__ void red2_kernel(const float* __restrict__ W3, const float* __restrict__ b3,
                            const float* __restrict__ h0, float* __restrict__ out,
                            int T, int nch) {
    __shared__ float Sz[HID];
    int i = threadIdx.x;
    float s = 0.f;
    for (int ch = 0; ch < nch; ch++) s += g_zc[ch * HID + i];
    Sz[i] = s;
    __syncthreads();
    if (i < HDIM) {
        float acc = (float)T * b3[i];
#pragma unroll
        for (int j = 0; j < HID; j++) acc = fmaf(W3[i * HID + j], Sz[j], acc);
        out[3 * T + i] = fmaf(DTC, acc, h0[i]);
    }
}

extern "C" void kernel_launch(void* const* d_in, const int* in_sizes, int n_in,
                              void* d_out, int out_size) {
    const float* U  = (const float*)d_in[0];
    const float* W1 = (const float*)d_in[1];
    const float* b1 = (const float*)d_in[2];
    const float* W2 = (const float*)d_in[3];
    const float* b2 = (const float*)d_in[4];
    const float* W3 = (const float*)d_in[5];
    const float* b3 = (const float*)d_in[6];
    const float* wd = (const float*)d_in[7];
    const float* bd = (const float*)d_in[8];
    const float* wt = (const float*)d_in[9];
    const float* bt = (const float*)d_in[10];
    const float* wc = (const float*)d_in[11];
    const float* bc = (const float*)d_in[12];
    const float* h0 = (const float*)d_in[13];
    float* out = (float*)d_out;

    int T = in_sizes[0] / UDIM;
    if (T > TMAX) T = TMAX;
    int nch = (T + CHUNK - 1) / CHUNK;

    pre_kernel<<<((T + 8) * HID + 255) / 256, 256>>>(U, W1, b1, T);
    prep_kernel<<<1, 128>>>(W3, wd, bd, wt, bt, wc, bc, b3, h0);
    probe_kernel<<<1, 32>>>();   // keeps seq_kernel in ncu's captured launch slot
    seq_kernel<<<1, 128>>>(W1, b2, W2, W3, b3, h0, T);
    post1_kernel<<<(T + 255) / 256, 256>>>(T);
    scan1_kernel<<<nch, CHUNK>>>(T);
    scan2_kernel<<<1, 4>>>(nch);
    scan3_kernel<<<(T + 255) / 256, 256>>>(out, T);
    red1_kernel<<<nch, HID>>>(T);
    red2_kernel<<<1, HID>>>(W3, b3, h0, out, T, nch);
}